// round 16
// baseline (speedup 1.0000x reference)
#include <cuda_runtime.h>
#include <cstdint>

#define F 128
#define F4 (F/4)
#define MAX_ATOMS 20000
#define MAX_PAIRS 320000
#define SCAN_THREADS 1024
#define SCAN_PER ((MAX_ATOMS + SCAN_THREADS - 1) / SCAN_THREADS)   // 20

#define FW 8                 // warps per fused block

typedef unsigned long long u64;

// Scratch (allocation-free rule: __device__ globals; zero-init at load;
// g_cnt restored to zero by scan_kernel every run)
__device__ int        g_cnt[MAX_ATOMS];          // hist counters (self-zeroing)
__device__ int        g_cnt2[MAX_ATOMS];         // stable copy of counts
__device__ int        g_off[MAX_ATOMS];          // bin offsets
__device__ int        g_pos[MAX_PAIRS];          // within-bin position
__device__ int        g_recJ[MAX_PAIRS];         // binned neighbor index
__device__ ulonglong4 g_recP[MAX_PAIRS];         // packed ((xc,xc),(yc,yc),(zc,zc),(c,c))

__device__ __forceinline__ u64 pack64(float a, float b) {
    u64 r; asm("mov.b64 %0, {%1, %2};" : "=l"(r) : "f"(a), "f"(b)); return r;
}
__device__ __forceinline__ float2 unpack64(u64 v) {
    float2 r; asm("mov.b64 {%0, %1}, %2;" : "=f"(r.x), "=f"(r.y) : "l"(v)); return r;
}
#define FMA2(acc, a, b) asm("fma.rn.f32x2 %0, %1, %2, %0;" : "+l"(acc) : "l"(a), "l"(b))

// ---------------------------------------------------------------------------
// K1: prep = histogram + within-bin positions
// ---------------------------------------------------------------------------
__global__ void prep_kernel(const int* __restrict__ pl, int n_pairs) {
    int p = blockIdx.x * blockDim.x + threadIdx.x;
    if (p < n_pairs) g_pos[p] = atomicAdd(&g_cnt[pl[p]], 1);
}

// ---------------------------------------------------------------------------
// K2: exclusive scan g_cnt -> g_off; copy counts to g_cnt2; zero g_cnt
// ---------------------------------------------------------------------------
__global__ void scan_kernel(int n_atoms) {
    __shared__ int ssum[SCAN_THREADS];
    int t = threadIdx.x;
    int base = t * SCAN_PER;
    int local[SCAN_PER];
    int s = 0;
#pragma unroll
    for (int k = 0; k < SCAN_PER; k++) {
        int idx = base + k;
        int v = 0;
        if (idx < n_atoms) {
            v = g_cnt[idx];
            g_cnt[idx] = 0;
            g_cnt2[idx] = v;
        }
        local[k] = s;
        s += v;
    }
    ssum[t] = s;
    __syncthreads();
    for (int d = 1; d < SCAN_THREADS; d <<= 1) {
        int x = (t >= d) ? ssum[t - d] : 0;
        __syncthreads();
        ssum[t] += x;
        __syncthreads();
    }
    int excl = (t > 0) ? ssum[t - 1] : 0;
#pragma unroll
    for (int k = 0; k < SCAN_PER; k++) {
        int idx = base + k;
        if (idx < n_atoms) g_off[idx] = excl + local[k];
    }
}

// ---------------------------------------------------------------------------
// K3: scatter pairs into bins; PRE-SCALED, PRE-PACKED records (proven)
// ---------------------------------------------------------------------------
__global__ void scatter_kernel(const int* __restrict__ pl,
                               const float* __restrict__ cut,
                               const float* __restrict__ rij,
                               int n_pairs) {
    int p = blockIdx.x * blockDim.x + threadIdx.x;
    if (p >= n_pairs) return;
    int   i = pl[p];
    int   j = pl[n_pairs + p];
    float c = cut[p];
    float r0 = rij[3 * p + 0];
    float r1 = rij[3 * p + 1];
    float r2 = rij[3 * p + 2];
    float s = rsqrtf(r0 * r0 + r1 * r1 + r2 * r2) * c;
    int pos = g_off[i] + g_pos[p];
    float xc = r0 * s, yc = r1 * s, zc = r2 * s;
    ulonglong4 rec;
    rec.x = pack64(xc, xc);
    rec.y = pack64(yc, yc);
    rec.z = pack64(zc, zc);
    rec.w = pack64(c, c);
    g_recJ[pos] = j;
    g_recP[pos] = rec;
}

// ---------------------------------------------------------------------------
// K4: FUSED gather + GEMM + norm. One warp per TWO atoms (grid-stride).
// Phase 1 (proven gather body) per atom; V -> per-warp smem slices.
// Phase 2: one in-warp GEMM pass for both atoms — W loads amortized 2x,
// W stored XOR-swizzled (conflict-free LDS.64). Norm+bias epilogue in-reg.
// ---------------------------------------------------------------------------
struct Acc2 { u64 r0, r1, x0, x1, y0, y1, z0, z1; };

__device__ __forceinline__ void accP(const ulonglong4& u, const ulonglong2& a, Acc2& s) {
    FMA2(s.r0, u.w, a.x); FMA2(s.r1, u.w, a.y);
    FMA2(s.x0, u.x, a.x); FMA2(s.x1, u.x, a.y);
    FMA2(s.y0, u.y, a.x); FMA2(s.y1, u.y, a.y);
    FMA2(s.z0, u.z, a.x); FMA2(s.z1, u.z, a.y);
}

__global__ __launch_bounds__(FW * 32, 2)
void fused_kernel(const ulonglong2* __restrict__ A2,
                  const float* __restrict__ Wm,
                  const float* __restrict__ bias,
                  float* __restrict__ out, int n_atoms) {
    extern __shared__ char smraw[];
    u64*        Ws  = (u64*)smraw;                       // [128*64] XOR-swizzled
    u64*        Vex = Ws + F * 64;                       // [FW][384] (2 atoms)
    int*        sJb = (int*)(Vex + FW * 384);            // [FW][32]
    ulonglong4* sPb = (ulonglong4*)(sJb + FW * 32);      // [FW][32]

    int t = threadIdx.x;
    int warp = t >> 5, lane = t & 31;

    // stage W rows XOR-swizzled: Ws[g*64 + (fh ^ (g&63))] = W[g][2fh:2fh+2]
    {
        const u64* Wg = (const u64*)Wm;
        for (int k = t; k < F * 64; k += FW * 32) {
            int g = k >> 6, fh = k & 63;
            Ws[g * 64 + (fh ^ (g & 63))] = Wg[k];
        }
    }
    __syncthreads();

    u64*        myV = Vex + warp * 384;
    int*        mJ  = sJb + warp * 32;
    ulonglong4* mP  = sPb + warp * 32;

    // precompute swizzled W base/mask for this lane's 4 columns
    int gbase[4], gmask[4];
#pragma unroll
    for (int m = 0; m < 4; m++) {
        int g = lane + 32 * m;
        gbase[m] = g * 64;
        gmask[m] = g & 63;
    }

    int wstride = gridDim.x * FW * 2;

    for (int w0 = (blockIdx.x * FW + warp) * 2; w0 < n_atoms; w0 += wstride) {
        int ncnt[2];

        // ---- Phase 1: gather, for both atoms ----
#pragma unroll 1
        for (int b = 0; b < 2; b++) {
            int w = w0 + b;
            if (w >= n_atoms) { ncnt[b] = 0; continue; }
            int n = g_cnt2[w];
            ncnt[b] = n;
            int base = g_off[w];

            Acc2 s = {};
            for (int c0 = 0; c0 < n; c0 += 32) {
                int m = n - c0; if (m > 32) m = 32;
                if (lane < m) {
                    mJ[lane] = g_recJ[base + c0 + lane];
                    mP[lane] = g_recP[base + c0 + lane];
                }
                __syncwarp();
                int k = 0;
                for (; k + 4 <= m; k += 4) {
                    int j0 = mJ[k + 0];
                    int j1 = mJ[k + 1];
                    int j2 = mJ[k + 2];
                    int j3 = mJ[k + 3];
                    ulonglong2 a0 = __ldg(&A2[j0 * F4 + lane]);
                    ulonglong2 a1 = __ldg(&A2[j1 * F4 + lane]);
                    ulonglong2 a2 = __ldg(&A2[j2 * F4 + lane]);
                    ulonglong2 a3 = __ldg(&A2[j3 * F4 + lane]);
                    accP(mP[k + 0], a0, s);
                    accP(mP[k + 1], a1, s);
                    accP(mP[k + 2], a2, s);
                    accP(mP[k + 3], a3, s);
                }
                for (; k < m; k++) {
                    int j0 = mJ[k];
                    ulonglong2 a0 = __ldg(&A2[j0 * F4 + lane]);
                    accP(mP[k], a0, s);
                }
                __syncwarp();
            }

            // radial half straight to gmem
            float2 p0 = unpack64(s.r0), p1 = unpack64(s.r1);
            *(float4*)(out + w * (2 * F) + F + lane * 4) =
                make_float4(p0.x, p0.y, p1.x, p1.y);

            // V -> smem slice b (lane l holds f = 4l..4l+3 per channel)
            u64* vb = myV + b * 192;
            ulonglong2 q;
            q.x = s.x0; q.y = s.x1; *(ulonglong2*)&vb[0 * 64 + 2 * lane] = q;
            q.x = s.y0; q.y = s.y1; *(ulonglong2*)&vb[1 * 64 + 2 * lane] = q;
            q.x = s.z0; q.y = s.z1; *(ulonglong2*)&vb[2 * 64 + 2 * lane] = q;
        }
        __syncwarp();

        // ---- Phase 2: in-warp linear layer for BOTH atoms ----
        u64 acc[2][3][4] = {};
#pragma unroll 4
        for (int fh = 0; fh < 64; fh++) {
            u64 wv[4];
#pragma unroll
            for (int m = 0; m < 4; m++)
                wv[m] = Ws[gbase[m] + (fh ^ gmask[m])];
            u64 v00 = myV[fh],        v01 = myV[64 + fh],  v02 = myV[128 + fh];
            u64 v10 = myV[192 + fh],  v11 = myV[256 + fh], v12 = myV[320 + fh];
#pragma unroll
            for (int m = 0; m < 4; m++) {
                FMA2(acc[0][0][m], v00, wv[m]);
                FMA2(acc[0][1][m], v01, wv[m]);
                FMA2(acc[0][2][m], v02, wv[m]);
                FMA2(acc[1][0][m], v10, wv[m]);
                FMA2(acc[1][1][m], v11, wv[m]);
                FMA2(acc[1][2][m], v12, wv[m]);
            }
        }

#pragma unroll
        for (int b = 0; b < 2; b++) {
            int w = w0 + b;
            if (w >= n_atoms) continue;
            float cnt = (float)ncnt[b];
#pragma unroll
            for (int m = 0; m < 4; m++) {
                int g = lane + 32 * m;
                float bb = __ldg(&bias[g]) * cnt;
                float2 px = unpack64(acc[b][0][m]);
                float2 py = unpack64(acc[b][1][m]);
                float2 pz = unpack64(acc[b][2][m]);
                float x = px.x + px.y + bb;
                float y = py.x + py.y + bb;
                float z = pz.x + pz.y + bb;
                out[w * (2 * F) + g] = sqrtf(x * x + y * y + z * z + 1e-12f);
            }
        }
        __syncwarp();   // myV/mJ/mP safe to overwrite next iteration
    }
}

// ---------------------------------------------------------------------------
// Launch (4 kernels)
// ---------------------------------------------------------------------------
extern "C" void kernel_launch(void* const* d_in, const int* in_sizes, int n_in,
                              void* d_out, int out_size) {
    const float* A   = (const float*)d_in[0];   // [N, F]
    const int*   pl  = (const int*)  d_in[1];   // [2, P]
    const float* cut = (const float*)d_in[2];   // [P, 1]
    const float* rij = (const float*)d_in[3];   // [P, 3]
    const float* Wm  = (const float*)d_in[4];   // [F, F]
    const float* b   = (const float*)d_in[5];   // [F]
    float* out = (float*)d_out;                 // [N, 2F]

    int n_atoms = in_sizes[0] / F;
    int n_pairs = in_sizes[2];

    prep_kernel<<<(n_pairs + 255) / 256, 256>>>(pl, n_pairs);

    scan_kernel<<<1, SCAN_THREADS>>>(n_atoms);

    scatter_kernel<<<(n_pairs + 255) / 256, 256>>>(pl, cut, rij, n_pairs);

    {
        int smem = F * 64 * 8              // W: 65,536 B (swizzled, no pad)
                 + FW * 384 * 8            // V exchange (2 atoms): 24,576 B
                 + FW * 32 * 4             // sJ: 1,024 B
                 + FW * 32 * 32;           // sP: 8,192 B  -> 99,328 B total
        cudaFuncSetAttribute(fused_kernel,
                             cudaFuncAttributeMaxDynamicSharedMemorySize, smem);
        fused_kernel<<<296, FW * 32, smem>>>((const ulonglong2*)A, Wm, b, out, n_atoms);
    }
}

// round 17
// speedup vs baseline: 1.0521x; 1.0521x over previous
#include <cuda_runtime.h>
#include <cstdint>

#define F 128
#define F4 (F/4)
#define MAX_ATOMS 20000
#define MAX_PAIRS 320000
#define SCAN_THREADS 1024
#define SCAN_PER ((MAX_ATOMS + SCAN_THREADS - 1) / SCAN_THREADS)   // 20

#define FW 8                 // warps per fused block
#define WROW 66              // u64 stride per W row: 528B, 16B-aligned,
                             // 528 mod 128 = 16 -> LDS.128 conflict-free

typedef unsigned long long u64;

// Scratch (allocation-free rule: __device__ globals; zero-init at load;
// g_cnt restored to zero by scan_kernel every run)
__device__ int        g_cnt[MAX_ATOMS];          // hist counters (self-zeroing)
__device__ int        g_cnt2[MAX_ATOMS];         // stable copy of counts
__device__ int        g_off[MAX_ATOMS];          // bin offsets
__device__ int        g_pos[MAX_PAIRS];          // within-bin position
__device__ int        g_recJ[MAX_PAIRS];         // binned neighbor index
__device__ ulonglong4 g_recP[MAX_PAIRS];         // packed ((xc,xc),(yc,yc),(zc,zc),(c,c))

__device__ __forceinline__ u64 pack64(float a, float b) {
    u64 r; asm("mov.b64 %0, {%1, %2};" : "=l"(r) : "f"(a), "f"(b)); return r;
}
__device__ __forceinline__ float2 unpack64(u64 v) {
    float2 r; asm("mov.b64 {%0, %1}, %2;" : "=f"(r.x), "=f"(r.y) : "l"(v)); return r;
}
#define FMA2(acc, a, b) asm("fma.rn.f32x2 %0, %1, %2, %0;" : "+l"(acc) : "l"(a), "l"(b))

// ---------------------------------------------------------------------------
// K1: prep = histogram + within-bin positions
// ---------------------------------------------------------------------------
__global__ void prep_kernel(const int* __restrict__ pl, int n_pairs) {
    int p = blockIdx.x * blockDim.x + threadIdx.x;
    if (p < n_pairs) g_pos[p] = atomicAdd(&g_cnt[pl[p]], 1);
}

// ---------------------------------------------------------------------------
// K2: exclusive scan g_cnt -> g_off; copy counts to g_cnt2; zero g_cnt
// ---------------------------------------------------------------------------
__global__ void scan_kernel(int n_atoms) {
    __shared__ int ssum[SCAN_THREADS];
    int t = threadIdx.x;
    int base = t * SCAN_PER;
    int local[SCAN_PER];
    int s = 0;
#pragma unroll
    for (int k = 0; k < SCAN_PER; k++) {
        int idx = base + k;
        int v = 0;
        if (idx < n_atoms) {
            v = g_cnt[idx];
            g_cnt[idx] = 0;
            g_cnt2[idx] = v;
        }
        local[k] = s;
        s += v;
    }
    ssum[t] = s;
    __syncthreads();
    for (int d = 1; d < SCAN_THREADS; d <<= 1) {
        int x = (t >= d) ? ssum[t - d] : 0;
        __syncthreads();
        ssum[t] += x;
        __syncthreads();
    }
    int excl = (t > 0) ? ssum[t - 1] : 0;
#pragma unroll
    for (int k = 0; k < SCAN_PER; k++) {
        int idx = base + k;
        if (idx < n_atoms) g_off[idx] = excl + local[k];
    }
}

// ---------------------------------------------------------------------------
// K3: scatter pairs into bins; PRE-SCALED, PRE-PACKED records (proven)
// ---------------------------------------------------------------------------
__global__ void scatter_kernel(const int* __restrict__ pl,
                               const float* __restrict__ cut,
                               const float* __restrict__ rij,
                               int n_pairs) {
    int p = blockIdx.x * blockDim.x + threadIdx.x;
    if (p >= n_pairs) return;
    int   i = pl[p];
    int   j = pl[n_pairs + p];
    float c = cut[p];
    float r0 = rij[3 * p + 0];
    float r1 = rij[3 * p + 1];
    float r2 = rij[3 * p + 2];
    float s = rsqrtf(r0 * r0 + r1 * r1 + r2 * r2) * c;
    int pos = g_off[i] + g_pos[p];
    float xc = r0 * s, yc = r1 * s, zc = r2 * s;
    ulonglong4 rec;
    rec.x = pack64(xc, xc);
    rec.y = pack64(yc, yc);
    rec.z = pack64(zc, zc);
    rec.w = pack64(c, c);
    g_recJ[pos] = j;
    g_recP[pos] = rec;
}

// ---------------------------------------------------------------------------
// K4: FUSED gather + GEMM + norm. One warp per TWO atoms (grid-stride).
// Phase 1 (proven body) per atom; V -> per-warp smem slices.
// Phase 2: in-warp GEMM, LDS.128 W loads (conflict-free via WROW=66),
// LDS.128 broadcast V loads, 2-fh steps. Norm+bias epilogue in-reg.
// ---------------------------------------------------------------------------
struct Acc2 { u64 r0, r1, x0, x1, y0, y1, z0, z1; };

__device__ __forceinline__ void accP(const ulonglong4& u, const ulonglong2& a, Acc2& s) {
    FMA2(s.r0, u.w, a.x); FMA2(s.r1, u.w, a.y);
    FMA2(s.x0, u.x, a.x); FMA2(s.x1, u.x, a.y);
    FMA2(s.y0, u.y, a.x); FMA2(s.y1, u.y, a.y);
    FMA2(s.z0, u.z, a.x); FMA2(s.z1, u.z, a.y);
}

__global__ __launch_bounds__(FW * 32, 2)
void fused_kernel(const ulonglong2* __restrict__ A2,
                  const float* __restrict__ Wm,
                  const float* __restrict__ bias,
                  float* __restrict__ out, int n_atoms) {
    extern __shared__ char smraw[];
    u64*        Ws  = (u64*)smraw;                       // [128][WROW]
    u64*        Vex = Ws + F * WROW;                     // [FW][384]
    int*        sJb = (int*)(Vex + FW * 384);            // [FW][32]
    ulonglong4* sPb = (ulonglong4*)(sJb + FW * 32);      // [FW][32]

    int t = threadIdx.x;
    int warp = t >> 5, lane = t & 31;

    // stage W rows (row-major, natural u64 pairs), padded stride 66
    {
        const u64* Wg = (const u64*)Wm;
        for (int k = t; k < F * 64; k += FW * 32) {
            int g = k >> 6, fh = k & 63;
            Ws[g * WROW + fh] = Wg[k];
        }
    }
    __syncthreads();

    u64*        myV = Vex + warp * 384;
    int*        mJ  = sJb + warp * 32;
    ulonglong4* mP  = sPb + warp * 32;

    const ulonglong2* W2 = (const ulonglong2*)Ws;   // row stride 33 ull2
    const ulonglong2* V2 = (const ulonglong2*)myV;  // 192 ull2

    int wstride = gridDim.x * FW * 2;

    for (int w0 = (blockIdx.x * FW + warp) * 2; w0 < n_atoms; w0 += wstride) {
        int ncnt[2];

        // ---- Phase 1: gather, for both atoms ----
#pragma unroll 1
        for (int b = 0; b < 2; b++) {
            int w = w0 + b;
            if (w >= n_atoms) { ncnt[b] = 0; continue; }
            int n = g_cnt2[w];
            ncnt[b] = n;
            int base = g_off[w];

            Acc2 s = {};
            for (int c0 = 0; c0 < n; c0 += 32) {
                int m = n - c0; if (m > 32) m = 32;
                if (lane < m) {
                    mJ[lane] = g_recJ[base + c0 + lane];
                    mP[lane] = g_recP[base + c0 + lane];
                }
                __syncwarp();
                int k = 0;
                for (; k + 4 <= m; k += 4) {
                    int j0 = mJ[k + 0];
                    int j1 = mJ[k + 1];
                    int j2 = mJ[k + 2];
                    int j3 = mJ[k + 3];
                    ulonglong2 a0 = __ldg(&A2[j0 * F4 + lane]);
                    ulonglong2 a1 = __ldg(&A2[j1 * F4 + lane]);
                    ulonglong2 a2 = __ldg(&A2[j2 * F4 + lane]);
                    ulonglong2 a3 = __ldg(&A2[j3 * F4 + lane]);
                    accP(mP[k + 0], a0, s);
                    accP(mP[k + 1], a1, s);
                    accP(mP[k + 2], a2, s);
                    accP(mP[k + 3], a3, s);
                }
                for (; k < m; k++) {
                    int j0 = mJ[k];
                    ulonglong2 a0 = __ldg(&A2[j0 * F4 + lane]);
                    accP(mP[k], a0, s);
                }
                __syncwarp();
            }

            // radial half straight to gmem
            float2 p0 = unpack64(s.r0), p1 = unpack64(s.r1);
            *(float4*)(out + w * (2 * F) + F + lane * 4) =
                make_float4(p0.x, p0.y, p1.x, p1.y);

            // V -> smem slice b (lane l holds f = 4l..4l+3 per channel)
            u64* vb = myV + b * 192;
            ulonglong2 q;
            q.x = s.x0; q.y = s.x1; *(ulonglong2*)&vb[0 * 64 + 2 * lane] = q;
            q.x = s.y0; q.y = s.y1; *(ulonglong2*)&vb[1 * 64 + 2 * lane] = q;
            q.x = s.z0; q.y = s.z1; *(ulonglong2*)&vb[2 * 64 + 2 * lane] = q;
        }
        __syncwarp();

        // ---- Phase 2: in-warp linear layer for BOTH atoms ----
        // lane handles cols g = lane + 32m; ull2 index fh2 covers f 4fh2..4fh2+3
        u64 acc[2][3][4] = {};
        int gr0 = (lane +  0) * 33;
        int gr1 = (lane + 32) * 33;
        int gr2 = (lane + 64) * 33;
        int gr3 = (lane + 96) * 33;
#pragma unroll 4
        for (int fh2 = 0; fh2 < 32; fh2++) {
            ulonglong2 wv0 = W2[gr0 + fh2];
            ulonglong2 wv1 = W2[gr1 + fh2];
            ulonglong2 wv2 = W2[gr2 + fh2];
            ulonglong2 wv3 = W2[gr3 + fh2];
            ulonglong2 va0 = V2[fh2];
            ulonglong2 va1 = V2[32 + fh2];
            ulonglong2 va2 = V2[64 + fh2];
            ulonglong2 vb0 = V2[96 + fh2];
            ulonglong2 vb1 = V2[128 + fh2];
            ulonglong2 vb2 = V2[160 + fh2];

            FMA2(acc[0][0][0], va0.x, wv0.x); FMA2(acc[0][0][0], va0.y, wv0.y);
            FMA2(acc[0][0][1], va0.x, wv1.x); FMA2(acc[0][0][1], va0.y, wv1.y);
            FMA2(acc[0][0][2], va0.x, wv2.x); FMA2(acc[0][0][2], va0.y, wv2.y);
            FMA2(acc[0][0][3], va0.x, wv3.x); FMA2(acc[0][0][3], va0.y, wv3.y);
            FMA2(acc[0][1][0], va1.x, wv0.x); FMA2(acc[0][1][0], va1.y, wv0.y);
            FMA2(acc[0][1][1], va1.x, wv1.x); FMA2(acc[0][1][1], va1.y, wv1.y);
            FMA2(acc[0][1][2], va1.x, wv2.x); FMA2(acc[0][1][2], va1.y, wv2.y);
            FMA2(acc[0][1][3], va1.x, wv3.x); FMA2(acc[0][1][3], va1.y, wv3.y);
            FMA2(acc[0][2][0], va2.x, wv0.x); FMA2(acc[0][2][0], va2.y, wv0.y);
            FMA2(acc[0][2][1], va2.x, wv1.x); FMA2(acc[0][2][1], va2.y, wv1.y);
            FMA2(acc[0][2][2], va2.x, wv2.x); FMA2(acc[0][2][2], va2.y, wv2.y);
            FMA2(acc[0][2][3], va2.x, wv3.x); FMA2(acc[0][2][3], va2.y, wv3.y);
            FMA2(acc[1][0][0], vb0.x, wv0.x); FMA2(acc[1][0][0], vb0.y, wv0.y);
            FMA2(acc[1][0][1], vb0.x, wv1.x); FMA2(acc[1][0][1], vb0.y, wv1.y);
            FMA2(acc[1][0][2], vb0.x, wv2.x); FMA2(acc[1][0][2], vb0.y, wv2.y);
            FMA2(acc[1][0][3], vb0.x, wv3.x); FMA2(acc[1][0][3], vb0.y, wv3.y);
            FMA2(acc[1][1][0], vb1.x, wv0.x); FMA2(acc[1][1][0], vb1.y, wv0.y);
            FMA2(acc[1][1][1], vb1.x, wv1.x); FMA2(acc[1][1][1], vb1.y, wv1.y);
            FMA2(acc[1][1][2], vb1.x, wv2.x); FMA2(acc[1][1][2], vb1.y, wv2.y);
            FMA2(acc[1][1][3], vb1.x, wv3.x); FMA2(acc[1][1][3], vb1.y, wv3.y);
            FMA2(acc[1][2][0], vb2.x, wv0.x); FMA2(acc[1][2][0], vb2.y, wv0.y);
            FMA2(acc[1][2][1], vb2.x, wv1.x); FMA2(acc[1][2][1], vb2.y, wv1.y);
            FMA2(acc[1][2][2], vb2.x, wv2.x); FMA2(acc[1][2][2], vb2.y, wv2.y);
            FMA2(acc[1][2][3], vb2.x, wv3.x); FMA2(acc[1][2][3], vb2.y, wv3.y);
        }

#pragma unroll
        for (int b = 0; b < 2; b++) {
            int w = w0 + b;
            if (w >= n_atoms) continue;
            float cnt = (float)ncnt[b];
#pragma unroll
            for (int m = 0; m < 4; m++) {
                int g = lane + 32 * m;
                float bb = __ldg(&bias[g]) * cnt;
                float2 px = unpack64(acc[b][0][m]);
                float2 py = unpack64(acc[b][1][m]);
                float2 pz = unpack64(acc[b][2][m]);
                float x = px.x + px.y + bb;
                float y = py.x + py.y + bb;
                float z = pz.x + pz.y + bb;
                out[w * (2 * F) + g] = sqrtf(x * x + y * y + z * z + 1e-12f);
            }
        }
        __syncwarp();   // myV/mJ/mP safe to overwrite next iteration
    }
}

// ---------------------------------------------------------------------------
// Launch (4 kernels)
// ---------------------------------------------------------------------------
extern "C" void kernel_launch(void* const* d_in, const int* in_sizes, int n_in,
                              void* d_out, int out_size) {
    const float* A   = (const float*)d_in[0];   // [N, F]
    const int*   pl  = (const int*)  d_in[1];   // [2, P]
    const float* cut = (const float*)d_in[2];   // [P, 1]
    const float* rij = (const float*)d_in[3];   // [P, 3]
    const float* Wm  = (const float*)d_in[4];   // [F, F]
    const float* b   = (const float*)d_in[5];   // [F]
    float* out = (float*)d_out;                 // [N, 2F]

    int n_atoms = in_sizes[0] / F;
    int n_pairs = in_sizes[2];

    prep_kernel<<<(n_pairs + 255) / 256, 256>>>(pl, n_pairs);

    scan_kernel<<<1, SCAN_THREADS>>>(n_atoms);

    scatter_kernel<<<(n_pairs + 255) / 256, 256>>>(pl, cut, rij, n_pairs);

    {
        int smem = F * WROW * 8            // W: 67,584 B
                 + FW * 384 * 8            // V exchange: 24,576 B
                 + FW * 32 * 4             // sJ: 1,024 B
                 + FW * 32 * 32;           // sP: 8,192 B  -> 101,376 B total
        cudaFuncSetAttribute(fused_kernel,
                             cudaFuncAttributeMaxDynamicSharedMemorySize, smem);
        fused_kernel<<<296, FW * 32, smem>>>((const ulonglong2*)A, Wm, b, out, n_atoms);
    }
}